// round 13
// baseline (speedup 1.0000x reference)
#include <cuda_runtime.h>
#include <cuda_bf16.h>
#include <math.h>
#include <stdint.h>

#define NN 100000
#define DD 256
#define HH 256
#define BB 128
#define EE 128
#define NSTEPS 5
#define BH (BB*HH)
#define NCHUNK 16
#define TS 64

typedef unsigned long long ull;

// ---------------- scratch (static device globals; no allocations) ----------------
__device__ float g_y1[(size_t)NN*HH];              // FNN intermediate (fp32)
__device__ __nv_bfloat162 g_hfb16[(size_t)NN*HH/2]; // FNN output, bf16 packed
__device__ float g_h[2*3*BH];                      // ping-pong [parity][layer]
__device__ float g_c[2*3*BH];
__device__ float g_qstar[BB*2*HH];
__device__ float g_rpart[(size_t)BB*NCHUNK*HH];
__device__ float g_spart[BB*NCHUNK];
__device__ float g_mpart[BB*NCHUNK];
__device__ int   g_seg[BB+1];

// ---------------- helpers ----------------
__device__ __forceinline__ float sigf(float x) { return 1.f / (1.f + expf(-x)); }

__device__ __forceinline__ void ffma2(ull &d, ull a, ull b) {
    asm("fma.rn.f32x2 %0, %1, %2, %3;" : "=l"(d) : "l"(a), "l"(b), "l"(d));
}
__device__ __forceinline__ ull bcast2(float a) {
    ull r;
    asm("mov.b64 %0, {%1, %1};" : "=l"(r) : "f"(a));
    return r;
}
__device__ __forceinline__ void unpack2(ull v, float &x, float &y) {
    asm("mov.b64 {%0, %1}, %2;" : "=f"(x), "=f"(y) : "l"(v));
}

// ---------------- init ----------------
__global__ void zero_state() {
    int i = blockIdx.x * blockDim.x + threadIdx.x;
    if (i < 2*3*BH) { g_h[i] = 0.f; g_c[i] = 0.f; }
    if (i < BB*2*HH) g_qstar[i] = 0.f;
}

__global__ void seg_bounds(const int* __restrict__ idx) {
    int b = threadIdx.x;
    if (b > BB) return;
    int lo = 0, hi = NN;
    while (lo < hi) { int mid = (lo + hi) >> 1; if (idx[mid] < b) lo = mid + 1; else hi = mid; }
    g_seg[b] = lo;
}

// ---------------- FNN GEMM: BM=128, BN=256 (full width), 8x16 thread tile ----------------
// 0.75 B/MAC smem traffic -> crossbar no longer co-limits FMA issue.
// FFMA2 pairing and k-order identical to the 8x8 version (bit-identical output).
template<int PHASE>
__global__ void __launch_bounds__(256, 1)
fnn_gemm(const float* __restrict__ Ax, const float* __restrict__ W,
         const float* __restrict__ bias) {
    const float* A = (PHASE == 0) ? Ax : g_y1;
    __shared__ float As[16*132];   // [k][m], padded stride 132
    __shared__ float Bs[16*256];   // [k][n], full 256-wide
    int tid = threadIdx.x;
    int m0 = blockIdx.x * 128;
    int tx = tid & 15, ty = tid >> 4;
    int c0 = tx * 8;               // first col group; second at c0+128
    int r0 = ty * 8;
    int arow = tid >> 2;           // 0..63
    int akq  = (tid & 3) * 4;      // 0,4,8,12
    int bk   = tid >> 5;           // 0..7
    int bnq  = (tid & 31) * 4;

    ull acc[8][8];                 // [row][pair]: pairs 0-3 = cols c0.., 4-7 = cols c0+128..
    #pragma unroll
    for (int i = 0; i < 8; i++)
        #pragma unroll
        for (int j = 0; j < 8; j++) acc[i][j] = 0ull;

    float4 pa0, pa1, pb[4];
    {
        int gm0 = m0 + arow, gm1 = m0 + arow + 64;
        pa0 = (gm0 < NN) ? *(const float4*)&A[(size_t)gm0*DD + akq] : make_float4(0,0,0,0);
        pa1 = (gm1 < NN) ? *(const float4*)&A[(size_t)gm1*DD + akq] : make_float4(0,0,0,0);
        pb[0] = *(const float4*)&W[(size_t)bk*HH + bnq];
        pb[1] = *(const float4*)&W[(size_t)(bk+8)*HH + bnq];
        pb[2] = *(const float4*)&W[(size_t)bk*HH + bnq + 128];
        pb[3] = *(const float4*)&W[(size_t)(bk+8)*HH + bnq + 128];
    }
    for (int kt = 0; kt < DD; kt += 16) {
        As[(akq+0)*132+arow] = pa0.x; As[(akq+1)*132+arow] = pa0.y;
        As[(akq+2)*132+arow] = pa0.z; As[(akq+3)*132+arow] = pa0.w;
        As[(akq+0)*132+arow+64] = pa1.x; As[(akq+1)*132+arow+64] = pa1.y;
        As[(akq+2)*132+arow+64] = pa1.z; As[(akq+3)*132+arow+64] = pa1.w;
        *(float4*)&Bs[bk*256 + bnq]           = pb[0];
        *(float4*)&Bs[(bk+8)*256 + bnq]       = pb[1];
        *(float4*)&Bs[bk*256 + bnq + 128]     = pb[2];
        *(float4*)&Bs[(bk+8)*256 + bnq + 128] = pb[3];
        __syncthreads();
        int kn = kt + 16;
        if (kn < DD) {
            int gm0 = m0 + arow, gm1 = m0 + arow + 64;
            pa0 = (gm0 < NN) ? *(const float4*)&A[(size_t)gm0*DD + kn + akq] : make_float4(0,0,0,0);
            pa1 = (gm1 < NN) ? *(const float4*)&A[(size_t)gm1*DD + kn + akq] : make_float4(0,0,0,0);
            pb[0] = *(const float4*)&W[(size_t)(kn+bk)*HH + bnq];
            pb[1] = *(const float4*)&W[(size_t)(kn+bk+8)*HH + bnq];
            pb[2] = *(const float4*)&W[(size_t)(kn+bk)*HH + bnq + 128];
            pb[3] = *(const float4*)&W[(size_t)(kn+bk+8)*HH + bnq + 128];
        }
        #pragma unroll
        for (int k = 0; k < 16; k++) {
            float a[8];
            *(float4*)&a[0] = *(const float4*)&As[k*132 + r0];
            *(float4*)&a[4] = *(const float4*)&As[k*132 + r0 + 4];
            ulonglong2 bq0 = *(const ulonglong2*)&Bs[k*256 + c0];
            ulonglong2 bq1 = *(const ulonglong2*)&Bs[k*256 + c0 + 4];
            ulonglong2 bq2 = *(const ulonglong2*)&Bs[k*256 + c0 + 128];
            ulonglong2 bq3 = *(const ulonglong2*)&Bs[k*256 + c0 + 132];
            #pragma unroll
            for (int i = 0; i < 8; i++) {
                ull ap = bcast2(a[i]);
                ffma2(acc[i][0], ap, bq0.x);
                ffma2(acc[i][1], ap, bq0.y);
                ffma2(acc[i][2], ap, bq1.x);
                ffma2(acc[i][3], ap, bq1.y);
                ffma2(acc[i][4], ap, bq2.x);
                ffma2(acc[i][5], ap, bq2.y);
                ffma2(acc[i][6], ap, bq3.x);
                ffma2(acc[i][7], ap, bq3.y);
            }
        }
        __syncthreads();
    }
    float bv0[8], bv1[8];
    #pragma unroll
    for (int j = 0; j < 8; j++) {
        bv0[j] = bias[c0 + j];
        bv1[j] = bias[c0 + 128 + j];
    }
    #pragma unroll
    for (int i = 0; i < 8; i++) {
        int gm = m0 + r0 + i;
        if (gm < NN) {
            float o0[8], o1[8];
            #pragma unroll
            for (int j = 0; j < 4; j++) {
                float x, y;
                unpack2(acc[i][j], x, y);
                float v0 = x + bv0[2*j], v1 = y + bv0[2*j+1];
                unpack2(acc[i][4+j], x, y);
                float w0 = x + bv1[2*j], w1 = y + bv1[2*j+1];
                if (PHASE == 0) {
                    v0 = (v0 > 0.f) ? v0 : expm1f(v0);
                    v1 = (v1 > 0.f) ? v1 : expm1f(v1);
                    w0 = (w0 > 0.f) ? w0 : expm1f(w0);
                    w1 = (w1 > 0.f) ? w1 : expm1f(w1);
                }
                o0[2*j] = v0; o0[2*j+1] = v1;
                o1[2*j] = w0; o1[2*j+1] = w1;
            }
            if (PHASE == 0) {
                *(float4*)&g_y1[(size_t)gm*HH + c0]           = *(float4*)&o0[0];
                *(float4*)&g_y1[(size_t)gm*HH + c0 + 4]       = *(float4*)&o0[4];
                *(float4*)&g_y1[(size_t)gm*HH + c0 + 128]     = *(float4*)&o1[0];
                *(float4*)&g_y1[(size_t)gm*HH + c0 + 132]     = *(float4*)&o1[4];
            } else {
                __nv_bfloat162 p0 = __float22bfloat162_rn(make_float2(o0[0], o0[1]));
                __nv_bfloat162 p1 = __float22bfloat162_rn(make_float2(o0[2], o0[3]));
                __nv_bfloat162 p2 = __float22bfloat162_rn(make_float2(o0[4], o0[5]));
                __nv_bfloat162 p3 = __float22bfloat162_rn(make_float2(o0[6], o0[7]));
                uint4 pk;
                pk.x = *(uint32_t*)&p0; pk.y = *(uint32_t*)&p1;
                pk.z = *(uint32_t*)&p2; pk.w = *(uint32_t*)&p3;
                *(uint4*)&g_hfb16[((size_t)gm*HH + c0) >> 1] = pk;
                p0 = __float22bfloat162_rn(make_float2(o1[0], o1[1]));
                p1 = __float22bfloat162_rn(make_float2(o1[2], o1[3]));
                p2 = __float22bfloat162_rn(make_float2(o1[4], o1[5]));
                p3 = __float22bfloat162_rn(make_float2(o1[6], o1[7]));
                pk.x = *(uint32_t*)&p0; pk.y = *(uint32_t*)&p1;
                pk.z = *(uint32_t*)&p2; pk.w = *(uint32_t*)&p3;
                *(uint4*)&g_hfb16[((size_t)gm*HH + c0 + 128) >> 1] = pk;
            }
        }
    }
}

// ---------------- fused LSTM layer: gates + cell, double-buffered W tiles ----------------
// grid (BB/8=16, HH/16=16), 128 threads. Thread (tx,ty) owns hcol t0+tx, all 4
// gates, batch b0+ty. W tile for kt+32 prefetched into regs during compute of kt.
__global__ void __launch_bounds__(128)
lstm_fused(int layer, int pr,
           const float* __restrict__ Wih, const float* __restrict__ Whh,
           const float* __restrict__ bih, const float* __restrict__ bhh) {
    __shared__ float As[8*768];     // [r][k], compact stride K
    __shared__ float Ws[2][32*68];  // double-buffered [k][j], j = 4*hcol_local + gate
    const int K1 = (layer == 0) ? 2*HH : HH;
    const int K  = K1 + HH;
    const int pw = pr ^ 1;
    const float* xin = (layer == 0) ? g_qstar : (g_h + (size_t)(pw*3 + (layer-1))*BH);
    const float* hin = g_h + (size_t)(pr*3 + layer)*BH;
    const float* cin = g_c + (size_t)(pr*3 + layer)*BH;
    float* hout = g_h + (size_t)(pw*3 + layer)*BH;
    float* cout = g_c + (size_t)(pw*3 + layer)*BH;
    int tid = threadIdx.x;
    int b0 = blockIdx.x * 8;
    int t0 = blockIdx.y * 16;       // h-column base
    int wj = tid >> 3;              // 0..15
    int wk = (tid & 7) * 4;         // 0,4,..28

    // A tile: all K for 8 batch rows
    for (int idx = tid; idx < 8*K; idx += 128) {
        int r = idx / K, k = idx - r*K;
        As[idx] = (k < K1) ? xin[(b0+r)*K1 + k] : hin[(b0+r)*HH + (k - K1)];
    }

    // prefetch W tile 0 into regs
    float4 wreg[4];
    {
        const float* Wsrc = Wih; int stride = K1, kc = wk;
        #pragma unroll
        for (int p = 0; p < 4; p++) {
            int j = p*16 + wj;
            int grow = (j & 3) * HH + t0 + (j >> 2);
            wreg[p] = *(const float4*)&Wsrc[(size_t)grow*stride + kc];
        }
    }
    // store tile 0
    #pragma unroll
    for (int p = 0; p < 4; p++) {
        int j = p*16 + wj;
        Ws[0][(wk+0)*68+j] = wreg[p].x; Ws[0][(wk+1)*68+j] = wreg[p].y;
        Ws[0][(wk+2)*68+j] = wreg[p].z; Ws[0][(wk+3)*68+j] = wreg[p].w;
    }
    __syncthreads();

    int tx = tid & 15, ty = tid >> 4;
    int c0 = tx * 4;
    float acc[4] = {0.f, 0.f, 0.f, 0.f};
    for (int kt = 0; kt < K; kt += 32) {
        int buf = (kt >> 5) & 1;
        bool more = (kt + 32) < K;
        // prefetch next tile into regs (latency hidden behind compute)
        if (more) {
            int ktn = kt + 32;
            const float* Wsrc; int stride, kc;
            if (ktn < K1) { Wsrc = Wih; stride = K1; kc = ktn + wk; }
            else          { Wsrc = Whh; stride = HH; kc = ktn - K1 + wk; }
            #pragma unroll
            for (int p = 0; p < 4; p++) {
                int j = p*16 + wj;
                int grow = (j & 3) * HH + t0 + (j >> 2);
                wreg[p] = *(const float4*)&Wsrc[(size_t)grow*stride + kc];
            }
        }
        const float* arow = As + ty*K + kt;
        const float* Wb = Ws[buf];
        #pragma unroll
        for (int k = 0; k < 32; k++) {
            float a = arow[k];
            float4 bv = *(const float4*)&Wb[k*68 + c0];
            acc[0] = fmaf(a, bv.x, acc[0]);
            acc[1] = fmaf(a, bv.y, acc[1]);
            acc[2] = fmaf(a, bv.z, acc[2]);
            acc[3] = fmaf(a, bv.w, acc[3]);
        }
        if (more) {
            float* Wn = Ws[buf ^ 1];
            #pragma unroll
            for (int p = 0; p < 4; p++) {
                int j = p*16 + wj;
                Wn[(wk+0)*68+j] = wreg[p].x; Wn[(wk+1)*68+j] = wreg[p].y;
                Wn[(wk+2)*68+j] = wreg[p].z; Wn[(wk+3)*68+j] = wreg[p].w;
            }
        }
        __syncthreads();
    }
    int b = b0 + ty, hcol = t0 + tx;
    float gi = acc[0] + bih[hcol]        + bhh[hcol];
    float gf = acc[1] + bih[HH + hcol]   + bhh[HH + hcol];
    float gg = acc[2] + bih[2*HH + hcol] + bhh[2*HH + hcol];
    float go = acc[3] + bih[3*HH + hcol] + bhh[3*HH + hcol];
    float cn = sigf(gf) * cin[b*HH + hcol] + sigf(gi) * tanhf(gg);
    float hn = sigf(go) * tanhf(cn);
    cout[b*HH + hcol] = cn;
    hout[b*HH + hcol] = hn;
    if (layer == 2) g_qstar[b*2*HH + hcol] = hn;
}

// ---------------- fused flash-style segment attention (bf16 hfeat, MLP-raised) ----------------
// grid (BB, NCHUNK), 256 threads.
__device__ __forceinline__ float dot_row_bf16(const uint4& v, const float* qb) {
    float2 h0 = __bfloat1622float2(*(__nv_bfloat162*)&v.x);
    float2 h1 = __bfloat1622float2(*(__nv_bfloat162*)&v.y);
    float2 h2 = __bfloat1622float2(*(__nv_bfloat162*)&v.z);
    float2 h3 = __bfloat1622float2(*(__nv_bfloat162*)&v.w);
    float sd = 0.f;
    sd = fmaf(h0.x, qb[0], sd); sd = fmaf(h0.y, qb[1], sd);
    sd = fmaf(h1.x, qb[2], sd); sd = fmaf(h1.y, qb[3], sd);
    sd = fmaf(h2.x, qb[4], sd); sd = fmaf(h2.y, qb[5], sd);
    sd = fmaf(h3.x, qb[6], sd); sd = fmaf(h3.y, qb[7], sd);
    return sd;
}

__global__ void __launch_bounds__(256)
attn_fused(int pw) {
    __shared__ float q[HH];
    __shared__ float se[TS];
    __shared__ float sw[TS];
    __shared__ float2 sacc[2][128];
    int b = blockIdx.x, p = blockIdx.y, t = threadIdx.x;
    int lane = t & 31, wid = t >> 5;
    q[t] = g_h[(size_t)(pw*3 + 2)*BH + b*HH + t];
    __syncthreads();
    int s = g_seg[b], e = g_seg[b+1], len = e - s;
    int c0 = s + (int)(((long long)len * p) / NCHUNK);
    int c1 = s + (int)(((long long)len * (p + 1)) / NCHUNK);

    int half = t >> 7, tt = t & 127;
    float M = -INFINITY, S = 0.f;
    float2 acc = make_float2(0.f, 0.f);
    for (int t0 = c0; t0 < c1; t0 += TS) {
        int tl = min(TS, c1 - t0);
        // pass A: warp per row, 2-row ILP (independent loads + interleaved shuffle chains)
        const float* qb = q + lane * 8;
        int i = wid;
        for (; i + 8 < tl; i += 16) {
            uint4 va = ((const uint4*)(g_hfb16 + (size_t)(t0 + i)     * (HH/2)))[lane];
            uint4 vb = ((const uint4*)(g_hfb16 + (size_t)(t0 + i + 8) * (HH/2)))[lane];
            float sda = dot_row_bf16(va, qb);
            float sdb = dot_row_bf16(vb, qb);
            #pragma unroll
            for (int o = 16; o > 0; o >>= 1) {
                sda += __shfl_xor_sync(0xffffffffu, sda, o);
                sdb += __shfl_xor_sync(0xffffffffu, sdb, o);
            }
            if (lane == 0) { se[i] = sda; se[i + 8] = sdb; }
        }
        for (; i < tl; i += 8) {
            uint4 v = ((const uint4*)(g_hfb16 + (size_t)(t0 + i) * (HH/2)))[lane];
            float sd = dot_row_bf16(v, qb);
            #pragma unroll
            for (int o = 16; o > 0; o >>= 1) sd += __shfl_xor_sync(0xffffffffu, sd, o);
            if (lane == 0) se[i] = sd;
        }
        __syncthreads();
        float mloc = -INFINITY;
        for (int k = 0; k < tl; k++) mloc = fmaxf(mloc, se[k]);
        float newM = fmaxf(M, mloc);
        float factor = expf(M - newM);
        if (t < tl) sw[t] = expf(se[t] - newM);
        acc.x *= factor; acc.y *= factor; S *= factor; M = newM;
        __syncthreads();
        // S (every thread, deterministic order)
        for (int k = 0; k < tl; k++) S += sw[k];
        // pass B: rows split between halves, unroll x4 (loads batched, FMA order preserved)
        const __nv_bfloat162* hb = g_hfb16 + tt;
        int j = half;
        for (; j + 6 < tl; j += 8) {
            float w0 = sw[j], w1 = sw[j+2], w2 = sw[j+4], w3 = sw[j+6];
            float2 h0 = __bfloat1622float2(hb[(size_t)(t0 + j)     * (HH/2)]);
            float2 h1 = __bfloat1622float2(hb[(size_t)(t0 + j + 2) * (HH/2)]);
            float2 h2 = __bfloat1622float2(hb[(size_t)(t0 + j + 4) * (HH/2)]);
            float2 h3 = __bfloat1622float2(hb[(size_t)(t0 + j + 6) * (HH/2)]);
            acc.x = fmaf(w0, h0.x, acc.x); acc.y = fmaf(w0, h0.y, acc.y);
            acc.x = fmaf(w1, h1.x, acc.x); acc.y = fmaf(w1, h1.y, acc.y);
            acc.x = fmaf(w2, h2.x, acc.x); acc.y = fmaf(w2, h2.y, acc.y);
            acc.x = fmaf(w3, h3.x, acc.x); acc.y = fmaf(w3, h3.y, acc.y);
        }
        for (; j < tl; j += 2) {
            float w = sw[j];
            float2 hv = __bfloat1622float2(hb[(size_t)(t0 + j) * (HH/2)]);
            acc.x = fmaf(w, hv.x, acc.x);
            acc.y = fmaf(w, hv.y, acc.y);
        }
        __syncthreads();
    }
    sacc[half][tt] = acc;
    __syncthreads();
    if (t < 128) {
        float2 a0 = sacc[0][t], a1 = sacc[1][t];
        float* dst = g_rpart + (size_t)(b * NCHUNK + p) * HH;
        dst[2*t]   = a0.x + a1.x;
        dst[2*t+1] = a0.y + a1.y;
    }
    if (t == 0) { g_spart[b * NCHUNK + p] = S; g_mpart[b * NCHUNK + p] = M; }
}

// combine partials with max-rescale -> r part of q_star
__global__ void __launch_bounds__(256)
attn_combine() {
    __shared__ float sm8[NCHUNK], ss8[NCHUNK];
    int b = blockIdx.x, t = threadIdx.x;
    if (t < NCHUNK) {
        sm8[t] = g_mpart[b * NCHUNK + t];
        ss8[t] = g_spart[b * NCHUNK + t];
    }
    __syncthreads();
    float Mg = -INFINITY;
    #pragma unroll
    for (int p = 0; p < NCHUNK; p++) Mg = fmaxf(Mg, sm8[p]);
    if (!isfinite(Mg)) Mg = 0.f;   // empty-segment guard (matches reference)
    float S = 0.f, r = 0.f;
    #pragma unroll
    for (int p = 0; p < NCHUNK; p++) {
        float f = expf(sm8[p] - Mg);
        S = fmaf(ss8[p], f, S);
        r = fmaf(g_rpart[(size_t)(b * NCHUNK + p) * HH + t], f, r);
    }
    g_qstar[b * 2 * HH + HH + t] = r / (S + 1e-16f);
}

// ---------------- output projection ----------------
__global__ void out_proj(const float* __restrict__ W, const float* __restrict__ bvec,
                         float* __restrict__ out) {
    __shared__ float qrow[2*HH];
    int b = blockIdx.x, t = threadIdx.x;    // 128 threads
    #pragma unroll
    for (int i = 0; i < 4; i++) qrow[t + i*128] = g_qstar[b*2*HH + t + i*128];
    __syncthreads();
    float acc = 0.f;
    #pragma unroll 8
    for (int k = 0; k < 2*HH; k++) acc = fmaf(qrow[k], W[k*EE + t], acc);
    out[b*EE + t] = acc + bvec[t];
}

// ---------------- launch ----------------
extern "C" void kernel_launch(void* const* d_in, const int* in_sizes, int n_in,
                              void* d_out, int out_size) {
    const float* x    = (const float*)d_in[0];
    const int*   bidx = (const int*)  d_in[1];
    const float* W1   = (const float*)d_in[2];
    const float* b1   = (const float*)d_in[3];
    const float* W2   = (const float*)d_in[4];
    const float* b2   = (const float*)d_in[5];
    const float* Wih[3] = {(const float*)d_in[6],  (const float*)d_in[10], (const float*)d_in[14]};
    const float* Whh[3] = {(const float*)d_in[7],  (const float*)d_in[11], (const float*)d_in[15]};
    const float* bih[3] = {(const float*)d_in[8],  (const float*)d_in[12], (const float*)d_in[16]};
    const float* bhh[3] = {(const float*)d_in[9],  (const float*)d_in[13], (const float*)d_in[17]};
    const float* outW = (const float*)d_in[18];
    const float* outb = (const float*)d_in[19];
    float* out = (float*)d_out;

    zero_state<<<(2*3*BH + 255)/256, 256>>>();
    seg_bounds<<<1, 256>>>(bidx);

    dim3 gfnn((NN + 127)/128);
    fnn_gemm<0><<<gfnn, 256>>>(x, W1, b1);
    fnn_gemm<1><<<gfnn, 256>>>(x, W2, b2);   // A ignored in phase 1 (reads g_y1)

    dim3 gl(BB/8, HH/16);
    dim3 gw(BB, NCHUNK);
    for (int s = 0; s < NSTEPS; s++) {
        int pr = s & 1;
        for (int l = 0; l < 3; l++)
            lstm_fused<<<gl, 128>>>(l, pr, Wih[l], Whh[l], bih[l], bhh[l]);
        attn_fused<<<gw, 256>>>(pr ^ 1);
        attn_combine<<<BB, 256>>>();
    }
    out_proj<<<BB, EE>>>(outW, outb, out);
}

// round 14
// speedup vs baseline: 1.0586x; 1.0586x over previous
#include <cuda_runtime.h>
#include <cuda_bf16.h>
#include <math.h>
#include <stdint.h>

#define NN 100000
#define DD 256
#define HH 256
#define BB 128
#define EE 128
#define NSTEPS 5
#define BH (BB*HH)
#define NCHUNK 16
#define TS 64

typedef unsigned long long ull;

// ---------------- scratch (static device globals; no allocations) ----------------
__device__ float g_y1[(size_t)NN*HH];              // FNN intermediate (fp32)
__device__ __nv_bfloat162 g_hfb16[(size_t)NN*HH/2]; // FNN output, bf16 packed
__device__ float g_h[2*3*BH];                      // ping-pong [parity][layer]
__device__ float g_c[2*3*BH];
__device__ float g_qstar[BB*2*HH];
__device__ float g_rpart[(size_t)BB*NCHUNK*HH];
__device__ float g_spart[BB*NCHUNK];
__device__ float g_mpart[BB*NCHUNK];
__device__ int   g_seg[BB+1];

// ---------------- helpers ----------------
__device__ __forceinline__ float sigf(float x) { return 1.f / (1.f + expf(-x)); }

__device__ __forceinline__ void ffma2(ull &d, ull a, ull b) {
    asm("fma.rn.f32x2 %0, %1, %2, %3;" : "=l"(d) : "l"(a), "l"(b), "l"(d));
}
__device__ __forceinline__ ull bcast2(float a) {
    ull r;
    asm("mov.b64 %0, {%1, %1};" : "=l"(r) : "f"(a));
    return r;
}
__device__ __forceinline__ void unpack2(ull v, float &x, float &y) {
    asm("mov.b64 {%0, %1}, %2;" : "=f"(x), "=f"(y) : "l"(v));
}

// ---------------- init ----------------
__global__ void zero_state() {
    int i = blockIdx.x * blockDim.x + threadIdx.x;
    if (i < 2*3*BH) { g_h[i] = 0.f; g_c[i] = 0.f; }
    if (i < BB*2*HH) g_qstar[i] = 0.f;
}

__global__ void seg_bounds(const int* __restrict__ idx) {
    int b = threadIdx.x;
    if (b > BB) return;
    int lo = 0, hi = NN;
    while (lo < hi) { int mid = (lo + hi) >> 1; if (idx[mid] < b) lo = mid + 1; else hi = mid; }
    g_seg[b] = lo;
}

// ---------------- FNN GEMM: 8x8 tile FFMA2 + double-buffered SMEM (1 barrier/tile) ----------------
template<int PHASE>
__global__ void __launch_bounds__(256, 2)
fnn_gemm(const float* __restrict__ Ax, const float* __restrict__ W,
         const float* __restrict__ bias) {
    const float* A = (PHASE == 0) ? Ax : g_y1;
    __shared__ float As[2][16*132];   // [buf][k][m], padded stride 132
    __shared__ float Bs[2][16*128];   // [buf][k][n]
    int tid = threadIdx.x;
    int m0 = blockIdx.x * 128;
    int n0 = blockIdx.y * 128;
    int tx = tid & 15, ty = tid >> 4;
    int c0 = tx * 8, r0 = ty * 8;
    int arow = tid >> 2;
    int akq  = (tid & 3) * 4;
    int bk   = tid >> 5;
    int bnq  = (tid & 31) * 4;

    ull acc[8][4];
    #pragma unroll
    for (int i = 0; i < 8; i++)
        #pragma unroll
        for (int j = 0; j < 4; j++) acc[i][j] = 0ull;

    float4 pa0, pa1, pb0, pb1;
    {
        int gm0 = m0 + arow, gm1 = m0 + arow + 64;
        pa0 = (gm0 < NN) ? *(const float4*)&A[(size_t)gm0*DD + akq] : make_float4(0,0,0,0);
        pa1 = (gm1 < NN) ? *(const float4*)&A[(size_t)gm1*DD + akq] : make_float4(0,0,0,0);
        pb0 = *(const float4*)&W[(size_t)bk*HH + n0 + bnq];
        pb1 = *(const float4*)&W[(size_t)(bk+8)*HH + n0 + bnq];
    }
    // store tile 0 into buf 0
    {
        float* A0 = As[0];
        float* B0 = Bs[0];
        A0[(akq+0)*132+arow] = pa0.x; A0[(akq+1)*132+arow] = pa0.y;
        A0[(akq+2)*132+arow] = pa0.z; A0[(akq+3)*132+arow] = pa0.w;
        A0[(akq+0)*132+arow+64] = pa1.x; A0[(akq+1)*132+arow+64] = pa1.y;
        A0[(akq+2)*132+arow+64] = pa1.z; A0[(akq+3)*132+arow+64] = pa1.w;
        *(float4*)&B0[bk*128 + bnq]     = pb0;
        *(float4*)&B0[(bk+8)*128 + bnq] = pb1;
    }
    __syncthreads();

    for (int kt = 0; kt < DD; kt += 16) {
        int buf = (kt >> 4) & 1;
        int kn = kt + 16;
        bool more = kn < DD;
        if (more) {
            int gm0 = m0 + arow, gm1 = m0 + arow + 64;
            pa0 = (gm0 < NN) ? *(const float4*)&A[(size_t)gm0*DD + kn + akq] : make_float4(0,0,0,0);
            pa1 = (gm1 < NN) ? *(const float4*)&A[(size_t)gm1*DD + kn + akq] : make_float4(0,0,0,0);
            pb0 = *(const float4*)&W[(size_t)(kn+bk)*HH + n0 + bnq];
            pb1 = *(const float4*)&W[(size_t)(kn+bk+8)*HH + n0 + bnq];
        }
        const float* Ab = As[buf];
        const float* Bb = Bs[buf];
        #pragma unroll
        for (int k = 0; k < 16; k++) {
            float a[8];
            *(float4*)&a[0] = *(const float4*)&Ab[k*132 + r0];
            *(float4*)&a[4] = *(const float4*)&Ab[k*132 + r0 + 4];
            ulonglong2 bq0 = *(const ulonglong2*)&Bb[k*128 + c0];
            ulonglong2 bq1 = *(const ulonglong2*)&Bb[k*128 + c0 + 4];
            ull bp0 = bq0.x, bp1 = bq0.y, bp2 = bq1.x, bp3 = bq1.y;
            #pragma unroll
            for (int i = 0; i < 8; i++) {
                ull ap = bcast2(a[i]);
                ffma2(acc[i][0], ap, bp0);
                ffma2(acc[i][1], ap, bp1);
                ffma2(acc[i][2], ap, bp2);
                ffma2(acc[i][3], ap, bp3);
            }
        }
        if (more) {
            float* An = As[buf ^ 1];
            float* Bn = Bs[buf ^ 1];
            An[(akq+0)*132+arow] = pa0.x; An[(akq+1)*132+arow] = pa0.y;
            An[(akq+2)*132+arow] = pa0.z; An[(akq+3)*132+arow] = pa0.w;
            An[(akq+0)*132+arow+64] = pa1.x; An[(akq+1)*132+arow+64] = pa1.y;
            An[(akq+2)*132+arow+64] = pa1.z; An[(akq+3)*132+arow+64] = pa1.w;
            *(float4*)&Bn[bk*128 + bnq]     = pb0;
            *(float4*)&Bn[(bk+8)*128 + bnq] = pb1;
        }
        __syncthreads();
    }
    float bv[8];
    #pragma unroll
    for (int j = 0; j < 8; j++) bv[j] = bias[n0 + c0 + j];
    #pragma unroll
    for (int i = 0; i < 8; i++) {
        int gm = m0 + r0 + i;
        if (gm < NN) {
            float o[8];
            #pragma unroll
            for (int j = 0; j < 4; j++) {
                float x, y;
                unpack2(acc[i][j], x, y);
                float v0 = x + bv[2*j], v1 = y + bv[2*j+1];
                if (PHASE == 0) {
                    v0 = (v0 > 0.f) ? v0 : expm1f(v0);
                    v1 = (v1 > 0.f) ? v1 : expm1f(v1);
                }
                o[2*j] = v0; o[2*j+1] = v1;
            }
            if (PHASE == 0) {
                *(float4*)&g_y1[(size_t)gm*HH + n0 + c0]     = *(float4*)&o[0];
                *(float4*)&g_y1[(size_t)gm*HH + n0 + c0 + 4] = *(float4*)&o[4];
            } else {
                __nv_bfloat162 p0 = __float22bfloat162_rn(make_float2(o[0], o[1]));
                __nv_bfloat162 p1 = __float22bfloat162_rn(make_float2(o[2], o[3]));
                __nv_bfloat162 p2 = __float22bfloat162_rn(make_float2(o[4], o[5]));
                __nv_bfloat162 p3 = __float22bfloat162_rn(make_float2(o[6], o[7]));
                uint4 pk;
                pk.x = *(uint32_t*)&p0; pk.y = *(uint32_t*)&p1;
                pk.z = *(uint32_t*)&p2; pk.w = *(uint32_t*)&p3;
                *(uint4*)&g_hfb16[((size_t)gm*HH + n0 + c0) >> 1] = pk;
            }
        }
    }
}

// ---------------- fused LSTM layer: gates + cell, double-buffered W tiles ----------------
// grid (BB/8=16, HH/16=16), 128 threads. Thread (tx,ty) owns hcol t0+tx, all 4
// gates, batch b0+ty. W tile for kt+32 prefetched into regs during compute of kt.
__global__ void __launch_bounds__(128)
lstm_fused(int layer, int pr,
           const float* __restrict__ Wih, const float* __restrict__ Whh,
           const float* __restrict__ bih, const float* __restrict__ bhh) {
    __shared__ float As[8*768];     // [r][k], compact stride K
    __shared__ float Ws[2][32*68];  // double-buffered [k][j], j = 4*hcol_local + gate
    const int K1 = (layer == 0) ? 2*HH : HH;
    const int K  = K1 + HH;
    const int pw = pr ^ 1;
    const float* xin = (layer == 0) ? g_qstar : (g_h + (size_t)(pw*3 + (layer-1))*BH);
    const float* hin = g_h + (size_t)(pr*3 + layer)*BH;
    const float* cin = g_c + (size_t)(pr*3 + layer)*BH;
    float* hout = g_h + (size_t)(pw*3 + layer)*BH;
    float* cout = g_c + (size_t)(pw*3 + layer)*BH;
    int tid = threadIdx.x;
    int b0 = blockIdx.x * 8;
    int t0 = blockIdx.y * 16;       // h-column base
    int wj = tid >> 3;              // 0..15
    int wk = (tid & 7) * 4;         // 0,4,..28

    // A tile: all K for 8 batch rows
    for (int idx = tid; idx < 8*K; idx += 128) {
        int r = idx / K, k = idx - r*K;
        As[idx] = (k < K1) ? xin[(b0+r)*K1 + k] : hin[(b0+r)*HH + (k - K1)];
    }

    // prefetch W tile 0 into regs
    float4 wreg[4];
    {
        const float* Wsrc = Wih; int stride = K1, kc = wk;
        #pragma unroll
        for (int p = 0; p < 4; p++) {
            int j = p*16 + wj;
            int grow = (j & 3) * HH + t0 + (j >> 2);
            wreg[p] = *(const float4*)&Wsrc[(size_t)grow*stride + kc];
        }
    }
    // store tile 0
    #pragma unroll
    for (int p = 0; p < 4; p++) {
        int j = p*16 + wj;
        Ws[0][(wk+0)*68+j] = wreg[p].x; Ws[0][(wk+1)*68+j] = wreg[p].y;
        Ws[0][(wk+2)*68+j] = wreg[p].z; Ws[0][(wk+3)*68+j] = wreg[p].w;
    }
    __syncthreads();

    int tx = tid & 15, ty = tid >> 4;
    int c0 = tx * 4;
    float acc[4] = {0.f, 0.f, 0.f, 0.f};
    for (int kt = 0; kt < K; kt += 32) {
        int buf = (kt >> 5) & 1;
        bool more = (kt + 32) < K;
        // prefetch next tile into regs (latency hidden behind compute)
        if (more) {
            int ktn = kt + 32;
            const float* Wsrc; int stride, kc;
            if (ktn < K1) { Wsrc = Wih; stride = K1; kc = ktn + wk; }
            else          { Wsrc = Whh; stride = HH; kc = ktn - K1 + wk; }
            #pragma unroll
            for (int p = 0; p < 4; p++) {
                int j = p*16 + wj;
                int grow = (j & 3) * HH + t0 + (j >> 2);
                wreg[p] = *(const float4*)&Wsrc[(size_t)grow*stride + kc];
            }
        }
        const float* arow = As + ty*K + kt;
        const float* Wb = Ws[buf];
        #pragma unroll
        for (int k = 0; k < 32; k++) {
            float a = arow[k];
            float4 bv = *(const float4*)&Wb[k*68 + c0];
            acc[0] = fmaf(a, bv.x, acc[0]);
            acc[1] = fmaf(a, bv.y, acc[1]);
            acc[2] = fmaf(a, bv.z, acc[2]);
            acc[3] = fmaf(a, bv.w, acc[3]);
        }
        if (more) {
            float* Wn = Ws[buf ^ 1];
            #pragma unroll
            for (int p = 0; p < 4; p++) {
                int j = p*16 + wj;
                Wn[(wk+0)*68+j] = wreg[p].x; Wn[(wk+1)*68+j] = wreg[p].y;
                Wn[(wk+2)*68+j] = wreg[p].z; Wn[(wk+3)*68+j] = wreg[p].w;
            }
        }
        __syncthreads();
    }
    int b = b0 + ty, hcol = t0 + tx;
    float gi = acc[0] + bih[hcol]        + bhh[hcol];
    float gf = acc[1] + bih[HH + hcol]   + bhh[HH + hcol];
    float gg = acc[2] + bih[2*HH + hcol] + bhh[2*HH + hcol];
    float go = acc[3] + bih[3*HH + hcol] + bhh[3*HH + hcol];
    float cn = sigf(gf) * cin[b*HH + hcol] + sigf(gi) * tanhf(gg);
    float hn = sigf(go) * tanhf(cn);
    cout[b*HH + hcol] = cn;
    hout[b*HH + hcol] = hn;
    if (layer == 2) g_qstar[b*2*HH + hcol] = hn;
}

// ---------------- fused flash-style segment attention (bf16 hfeat, MLP-raised) ----------------
// grid (BB, NCHUNK), 256 threads.
__device__ __forceinline__ float dot_row_bf16(const uint4& v, const float* qb) {
    float2 h0 = __bfloat1622float2(*(__nv_bfloat162*)&v.x);
    float2 h1 = __bfloat1622float2(*(__nv_bfloat162*)&v.y);
    float2 h2 = __bfloat1622float2(*(__nv_bfloat162*)&v.z);
    float2 h3 = __bfloat1622float2(*(__nv_bfloat162*)&v.w);
    float sd = 0.f;
    sd = fmaf(h0.x, qb[0], sd); sd = fmaf(h0.y, qb[1], sd);
    sd = fmaf(h1.x, qb[2], sd); sd = fmaf(h1.y, qb[3], sd);
    sd = fmaf(h2.x, qb[4], sd); sd = fmaf(h2.y, qb[5], sd);
    sd = fmaf(h3.x, qb[6], sd); sd = fmaf(h3.y, qb[7], sd);
    return sd;
}

__global__ void __launch_bounds__(256)
attn_fused(int pw) {
    __shared__ float q[HH];
    __shared__ float se[TS];
    __shared__ float sw[TS];
    __shared__ float2 sacc[2][128];
    int b = blockIdx.x, p = blockIdx.y, t = threadIdx.x;
    int lane = t & 31, wid = t >> 5;
    q[t] = g_h[(size_t)(pw*3 + 2)*BH + b*HH + t];
    __syncthreads();
    int s = g_seg[b], e = g_seg[b+1], len = e - s;
    int c0 = s + (int)(((long long)len * p) / NCHUNK);
    int c1 = s + (int)(((long long)len * (p + 1)) / NCHUNK);

    int half = t >> 7, tt = t & 127;
    float M = -INFINITY, S = 0.f;
    float2 acc = make_float2(0.f, 0.f);
    for (int t0 = c0; t0 < c1; t0 += TS) {
        int tl = min(TS, c1 - t0);
        // pass A: warp per row, 2-row ILP (independent loads + interleaved shuffle chains)
        const float* qb = q + lane * 8;
        int i = wid;
        for (; i + 8 < tl; i += 16) {
            uint4 va = ((const uint4*)(g_hfb16 + (size_t)(t0 + i)     * (HH/2)))[lane];
            uint4 vb = ((const uint4*)(g_hfb16 + (size_t)(t0 + i + 8) * (HH/2)))[lane];
            float sda = dot_row_bf16(va, qb);
            float sdb = dot_row_bf16(vb, qb);
            #pragma unroll
            for (int o = 16; o > 0; o >>= 1) {
                sda += __shfl_xor_sync(0xffffffffu, sda, o);
                sdb += __shfl_xor_sync(0xffffffffu, sdb, o);
            }
            if (lane == 0) { se[i] = sda; se[i + 8] = sdb; }
        }
        for (; i < tl; i += 8) {
            uint4 v = ((const uint4*)(g_hfb16 + (size_t)(t0 + i) * (HH/2)))[lane];
            float sd = dot_row_bf16(v, qb);
            #pragma unroll
            for (int o = 16; o > 0; o >>= 1) sd += __shfl_xor_sync(0xffffffffu, sd, o);
            if (lane == 0) se[i] = sd;
        }
        __syncthreads();
        float mloc = -INFINITY;
        for (int k = 0; k < tl; k++) mloc = fmaxf(mloc, se[k]);
        float newM = fmaxf(M, mloc);
        float factor = expf(M - newM);
        if (t < tl) sw[t] = expf(se[t] - newM);
        acc.x *= factor; acc.y *= factor; S *= factor; M = newM;
        __syncthreads();
        // S (every thread, deterministic order)
        for (int k = 0; k < tl; k++) S += sw[k];
        // pass B: rows split between halves, unroll x4 (loads batched, FMA order preserved)
        const __nv_bfloat162* hb = g_hfb16 + tt;
        int j = half;
        for (; j + 6 < tl; j += 8) {
            float w0 = sw[j], w1 = sw[j+2], w2 = sw[j+4], w3 = sw[j+6];
            float2 h0 = __bfloat1622float2(hb[(size_t)(t0 + j)     * (HH/2)]);
            float2 h1 = __bfloat1622float2(hb[(size_t)(t0 + j + 2) * (HH/2)]);
            float2 h2 = __bfloat1622float2(hb[(size_t)(t0 + j + 4) * (HH/2)]);
            float2 h3 = __bfloat1622float2(hb[(size_t)(t0 + j + 6) * (HH/2)]);
            acc.x = fmaf(w0, h0.x, acc.x); acc.y = fmaf(w0, h0.y, acc.y);
            acc.x = fmaf(w1, h1.x, acc.x); acc.y = fmaf(w1, h1.y, acc.y);
            acc.x = fmaf(w2, h2.x, acc.x); acc.y = fmaf(w2, h2.y, acc.y);
            acc.x = fmaf(w3, h3.x, acc.x); acc.y = fmaf(w3, h3.y, acc.y);
        }
        for (; j < tl; j += 2) {
            float w = sw[j];
            float2 hv = __bfloat1622float2(hb[(size_t)(t0 + j) * (HH/2)]);
            acc.x = fmaf(w, hv.x, acc.x);
            acc.y = fmaf(w, hv.y, acc.y);
        }
        __syncthreads();
    }
    sacc[half][tt] = acc;
    __syncthreads();
    if (t < 128) {
        float2 a0 = sacc[0][t], a1 = sacc[1][t];
        float* dst = g_rpart + (size_t)(b * NCHUNK + p) * HH;
        dst[2*t]   = a0.x + a1.x;
        dst[2*t+1] = a0.y + a1.y;
    }
    if (t == 0) { g_spart[b * NCHUNK + p] = S; g_mpart[b * NCHUNK + p] = M; }
}

// combine partials with max-rescale -> r part of q_star
__global__ void __launch_bounds__(256)
attn_combine() {
    __shared__ float sm8[NCHUNK], ss8[NCHUNK];
    int b = blockIdx.x, t = threadIdx.x;
    if (t < NCHUNK) {
        sm8[t] = g_mpart[b * NCHUNK + t];
        ss8[t] = g_spart[b * NCHUNK + t];
    }
    __syncthreads();
    float Mg = -INFINITY;
    #pragma unroll
    for (int p = 0; p < NCHUNK; p++) Mg = fmaxf(Mg, sm8[p]);
    if (!isfinite(Mg)) Mg = 0.f;   // empty-segment guard (matches reference)
    float S = 0.f, r = 0.f;
    #pragma unroll
    for (int p = 0; p < NCHUNK; p++) {
        float f = expf(sm8[p] - Mg);
        S = fmaf(ss8[p], f, S);
        r = fmaf(g_rpart[(size_t)(b * NCHUNK + p) * HH + t], f, r);
    }
    g_qstar[b * 2 * HH + HH + t] = r / (S + 1e-16f);
}

// ---------------- output projection ----------------
__global__ void out_proj(const float* __restrict__ W, const float* __restrict__ bvec,
                         float* __restrict__ out) {
    __shared__ float qrow[2*HH];
    int b = blockIdx.x, t = threadIdx.x;    // 128 threads
    #pragma unroll
    for (int i = 0; i < 4; i++) qrow[t + i*128] = g_qstar[b*2*HH + t + i*128];
    __syncthreads();
    float acc = 0.f;
    #pragma unroll 8
    for (int k = 0; k < 2*HH; k++) acc = fmaf(qrow[k], W[k*EE + t], acc);
    out[b*EE + t] = acc + bvec[t];
}

// ---------------- launch ----------------
extern "C" void kernel_launch(void* const* d_in, const int* in_sizes, int n_in,
                              void* d_out, int out_size) {
    const float* x    = (const float*)d_in[0];
    const int*   bidx = (const int*)  d_in[1];
    const float* W1   = (const float*)d_in[2];
    const float* b1   = (const float*)d_in[3];
    const float* W2   = (const float*)d_in[4];
    const float* b2   = (const float*)d_in[5];
    const float* Wih[3] = {(const float*)d_in[6],  (const float*)d_in[10], (const float*)d_in[14]};
    const float* Whh[3] = {(const float*)d_in[7],  (const float*)d_in[11], (const float*)d_in[15]};
    const float* bih[3] = {(const float*)d_in[8],  (const float*)d_in[12], (const float*)d_in[16]};
    const float* bhh[3] = {(const float*)d_in[9],  (const float*)d_in[13], (const float*)d_in[17]};
    const float* outW = (const float*)d_in[18];
    const float* outb = (const float*)d_in[19];
    float* out = (float*)d_out;

    zero_state<<<(2*3*BH + 255)/256, 256>>>();
    seg_bounds<<<1, 256>>>(bidx);

    dim3 gfnn((NN + 127)/128, HH/128);
    fnn_gemm<0><<<gfnn, 256>>>(x, W1, b1);
    fnn_gemm<1><<<gfnn, 256>>>(x, W2, b2);   // A ignored in phase 1 (reads g_y1)

    dim3 gl(BB/8, HH/16);
    dim3 gw(BB, NCHUNK);
    for (int s = 0; s < NSTEPS; s++) {
        int pr = s & 1;
        for (int l = 0; l < 3; l++)
            lstm_fused<<<gl, 128>>>(l, pr, Wih[l], Whh[l], bih[l], bhh[l]);
        attn_fused<<<gw, 256>>>(pr ^ 1);
        attn_combine<<<BB, 256>>>();
    }
    out_proj<<<BB, EE>>>(outW, outb, out);
}

// round 15
// speedup vs baseline: 1.0747x; 1.0152x over previous
#include <cuda_runtime.h>
#include <cuda_bf16.h>
#include <math.h>
#include <stdint.h>

#define NN 100000
#define DD 256
#define HH 256
#define BB 128
#define EE 128
#define NSTEPS 5
#define BH (BB*HH)
#define NCHUNK 16
#define TS 64

typedef unsigned long long ull;

// ---------------- scratch (static device globals; no allocations) ----------------
__device__ float g_y1[(size_t)NN*HH];              // FNN intermediate (fp32)
__device__ __nv_bfloat162 g_hfb16[(size_t)NN*HH/2]; // FNN output, bf16 packed
__device__ float g_h[2*3*BH];                      // ping-pong [parity][layer]
__device__ float g_c[2*3*BH];
__device__ float g_qstar[BB*2*HH];
__device__ float g_rpart[(size_t)BB*NCHUNK*HH];
__device__ float g_spart[BB*NCHUNK];
__device__ float g_mpart[BB*NCHUNK];
__device__ unsigned g_ctr[BB];                     // last-block-done counters
__device__ int   g_seg[BB+1];

// ---------------- helpers ----------------
__device__ __forceinline__ float sigf(float x) { return 1.f / (1.f + expf(-x)); }

__device__ __forceinline__ void ffma2(ull &d, ull a, ull b) {
    asm("fma.rn.f32x2 %0, %1, %2, %3;" : "=l"(d) : "l"(a), "l"(b), "l"(d));
}
__device__ __forceinline__ ull bcast2(float a) {
    ull r;
    asm("mov.b64 %0, {%1, %1};" : "=l"(r) : "f"(a));
    return r;
}
__device__ __forceinline__ void unpack2(ull v, float &x, float &y) {
    asm("mov.b64 {%0, %1}, %2;" : "=f"(x), "=f"(y) : "l"(v));
}

// ---------------- init ----------------
__global__ void zero_state() {
    int i = blockIdx.x * blockDim.x + threadIdx.x;
    if (i < 2*3*BH) { g_h[i] = 0.f; g_c[i] = 0.f; }
    if (i < BB*2*HH) g_qstar[i] = 0.f;
    if (i < BB) g_ctr[i] = 0u;
}

__global__ void seg_bounds(const int* __restrict__ idx) {
    int b = threadIdx.x;
    if (b > BB) return;
    int lo = 0, hi = NN;
    while (lo < hi) { int mid = (lo + hi) >> 1; if (idx[mid] < b) lo = mid + 1; else hi = mid; }
    g_seg[b] = lo;
}

// ---------------- FNN GEMM: proven round-12 FFMA2 kernel; phase 1 writes bf16 ----------------
template<int PHASE>
__global__ void __launch_bounds__(256, 2)
fnn_gemm(const float* __restrict__ Ax, const float* __restrict__ W,
         const float* __restrict__ bias) {
    const float* A = (PHASE == 0) ? Ax : g_y1;
    __shared__ float As[16*132];   // [k][m], padded stride 132
    __shared__ float Bs[16*128];   // [k][n]
    int tid = threadIdx.x;
    int m0 = blockIdx.x * 128;
    int n0 = blockIdx.y * 128;
    int tx = tid & 15, ty = tid >> 4;
    int c0 = tx * 8, r0 = ty * 8;
    int arow = tid >> 2;
    int akq  = (tid & 3) * 4;
    int bk   = tid >> 5;
    int bnq  = (tid & 31) * 4;

    ull acc[8][4];
    #pragma unroll
    for (int i = 0; i < 8; i++)
        #pragma unroll
        for (int j = 0; j < 4; j++) acc[i][j] = 0ull;

    float4 pa0, pa1, pb0, pb1;
    {
        int gm0 = m0 + arow, gm1 = m0 + arow + 64;
        pa0 = (gm0 < NN) ? *(const float4*)&A[(size_t)gm0*DD + akq] : make_float4(0,0,0,0);
        pa1 = (gm1 < NN) ? *(const float4*)&A[(size_t)gm1*DD + akq] : make_float4(0,0,0,0);
        pb0 = *(const float4*)&W[(size_t)bk*HH + n0 + bnq];
        pb1 = *(const float4*)&W[(size_t)(bk+8)*HH + n0 + bnq];
    }
    for (int kt = 0; kt < DD; kt += 16) {
        As[(akq+0)*132+arow] = pa0.x; As[(akq+1)*132+arow] = pa0.y;
        As[(akq+2)*132+arow] = pa0.z; As[(akq+3)*132+arow] = pa0.w;
        As[(akq+0)*132+arow+64] = pa1.x; As[(akq+1)*132+arow+64] = pa1.y;
        As[(akq+2)*132+arow+64] = pa1.z; As[(akq+3)*132+arow+64] = pa1.w;
        *(float4*)&Bs[bk*128 + bnq]     = pb0;
        *(float4*)&Bs[(bk+8)*128 + bnq] = pb1;
        __syncthreads();
        int kn = kt + 16;
        if (kn < DD) {
            int gm0 = m0 + arow, gm1 = m0 + arow + 64;
            pa0 = (gm0 < NN) ? *(const float4*)&A[(size_t)gm0*DD + kn + akq] : make_float4(0,0,0,0);
            pa1 = (gm1 < NN) ? *(const float4*)&A[(size_t)gm1*DD + kn + akq] : make_float4(0,0,0,0);
            pb0 = *(const float4*)&W[(size_t)(kn+bk)*HH + n0 + bnq];
            pb1 = *(const float4*)&W[(size_t)(kn+bk+8)*HH + n0 + bnq];
        }
        #pragma unroll
        for (int k = 0; k < 16; k++) {
            float a[8];
            *(float4*)&a[0] = *(const float4*)&As[k*132 + r0];
            *(float4*)&a[4] = *(const float4*)&As[k*132 + r0 + 4];
            ulonglong2 bq0 = *(const ulonglong2*)&Bs[k*128 + c0];
            ulonglong2 bq1 = *(const ulonglong2*)&Bs[k*128 + c0 + 4];
            ull bp0 = bq0.x, bp1 = bq0.y, bp2 = bq1.x, bp3 = bq1.y;
            #pragma unroll
            for (int i = 0; i < 8; i++) {
                ull ap = bcast2(a[i]);
                ffma2(acc[i][0], ap, bp0);
                ffma2(acc[i][1], ap, bp1);
                ffma2(acc[i][2], ap, bp2);
                ffma2(acc[i][3], ap, bp3);
            }
        }
        __syncthreads();
    }
    float bv[8];
    #pragma unroll
    for (int j = 0; j < 8; j++) bv[j] = bias[n0 + c0 + j];
    #pragma unroll
    for (int i = 0; i < 8; i++) {
        int gm = m0 + r0 + i;
        if (gm < NN) {
            float o[8];
            #pragma unroll
            for (int j = 0; j < 4; j++) {
                float x, y;
                unpack2(acc[i][j], x, y);
                float v0 = x + bv[2*j], v1 = y + bv[2*j+1];
                if (PHASE == 0) {
                    v0 = (v0 > 0.f) ? v0 : expm1f(v0);
                    v1 = (v1 > 0.f) ? v1 : expm1f(v1);
                }
                o[2*j] = v0; o[2*j+1] = v1;
            }
            if (PHASE == 0) {
                *(float4*)&g_y1[(size_t)gm*HH + n0 + c0]     = *(float4*)&o[0];
                *(float4*)&g_y1[(size_t)gm*HH + n0 + c0 + 4] = *(float4*)&o[4];
            } else {
                __nv_bfloat162 p0 = __float22bfloat162_rn(make_float2(o[0], o[1]));
                __nv_bfloat162 p1 = __float22bfloat162_rn(make_float2(o[2], o[3]));
                __nv_bfloat162 p2 = __float22bfloat162_rn(make_float2(o[4], o[5]));
                __nv_bfloat162 p3 = __float22bfloat162_rn(make_float2(o[6], o[7]));
                uint4 pk;
                pk.x = *(uint32_t*)&p0; pk.y = *(uint32_t*)&p1;
                pk.z = *(uint32_t*)&p2; pk.w = *(uint32_t*)&p3;
                *(uint4*)&g_hfb16[((size_t)gm*HH + n0 + c0) >> 1] = pk;
            }
        }
    }
}

// ---------------- fused LSTM layer: gates + cell, double-buffered W tiles ----------------
// grid (BB/8=16, HH/16=16), 128 threads. Thread (tx,ty) owns hcol t0+tx, all 4
// gates, batch b0+ty. W tile for kt+32 prefetched into regs during compute of kt.
__global__ void __launch_bounds__(128)
lstm_fused(int layer, int pr,
           const float* __restrict__ Wih, const float* __restrict__ Whh,
           const float* __restrict__ bih, const float* __restrict__ bhh) {
    __shared__ float As[8*768];     // [r][k], compact stride K
    __shared__ float Ws[2][32*68];  // double-buffered [k][j], j = 4*hcol_local + gate
    const int K1 = (layer == 0) ? 2*HH : HH;
    const int K  = K1 + HH;
    const int pw = pr ^ 1;
    const float* xin = (layer == 0) ? g_qstar : (g_h + (size_t)(pw*3 + (layer-1))*BH);
    const float* hin = g_h + (size_t)(pr*3 + layer)*BH;
    const float* cin = g_c + (size_t)(pr*3 + layer)*BH;
    float* hout = g_h + (size_t)(pw*3 + layer)*BH;
    float* cout = g_c + (size_t)(pw*3 + layer)*BH;
    int tid = threadIdx.x;
    int b0 = blockIdx.x * 8;
    int t0 = blockIdx.y * 16;       // h-column base
    int wj = tid >> 3;              // 0..15
    int wk = (tid & 7) * 4;         // 0,4,..28

    // A tile: all K for 8 batch rows
    for (int idx = tid; idx < 8*K; idx += 128) {
        int r = idx / K, k = idx - r*K;
        As[idx] = (k < K1) ? xin[(b0+r)*K1 + k] : hin[(b0+r)*HH + (k - K1)];
    }

    // prefetch W tile 0 into regs
    float4 wreg[4];
    {
        const float* Wsrc = Wih; int stride = K1, kc = wk;
        #pragma unroll
        for (int p = 0; p < 4; p++) {
            int j = p*16 + wj;
            int grow = (j & 3) * HH + t0 + (j >> 2);
            wreg[p] = *(const float4*)&Wsrc[(size_t)grow*stride + kc];
        }
    }
    // store tile 0
    #pragma unroll
    for (int p = 0; p < 4; p++) {
        int j = p*16 + wj;
        Ws[0][(wk+0)*68+j] = wreg[p].x; Ws[0][(wk+1)*68+j] = wreg[p].y;
        Ws[0][(wk+2)*68+j] = wreg[p].z; Ws[0][(wk+3)*68+j] = wreg[p].w;
    }
    __syncthreads();

    int tx = tid & 15, ty = tid >> 4;
    int c0 = tx * 4;
    float acc[4] = {0.f, 0.f, 0.f, 0.f};
    for (int kt = 0; kt < K; kt += 32) {
        int buf = (kt >> 5) & 1;
        bool more = (kt + 32) < K;
        // prefetch next tile into regs (latency hidden behind compute)
        if (more) {
            int ktn = kt + 32;
            const float* Wsrc; int stride, kc;
            if (ktn < K1) { Wsrc = Wih; stride = K1; kc = ktn + wk; }
            else          { Wsrc = Whh; stride = HH; kc = ktn - K1 + wk; }
            #pragma unroll
            for (int p = 0; p < 4; p++) {
                int j = p*16 + wj;
                int grow = (j & 3) * HH + t0 + (j >> 2);
                wreg[p] = *(const float4*)&Wsrc[(size_t)grow*stride + kc];
            }
        }
        const float* arow = As + ty*K + kt;
        const float* Wb = Ws[buf];
        #pragma unroll
        for (int k = 0; k < 32; k++) {
            float a = arow[k];
            float4 bv = *(const float4*)&Wb[k*68 + c0];
            acc[0] = fmaf(a, bv.x, acc[0]);
            acc[1] = fmaf(a, bv.y, acc[1]);
            acc[2] = fmaf(a, bv.z, acc[2]);
            acc[3] = fmaf(a, bv.w, acc[3]);
        }
        if (more) {
            float* Wn = Ws[buf ^ 1];
            #pragma unroll
            for (int p = 0; p < 4; p++) {
                int j = p*16 + wj;
                Wn[(wk+0)*68+j] = wreg[p].x; Wn[(wk+1)*68+j] = wreg[p].y;
                Wn[(wk+2)*68+j] = wreg[p].z; Wn[(wk+3)*68+j] = wreg[p].w;
            }
        }
        __syncthreads();
    }
    int b = b0 + ty, hcol = t0 + tx;
    float gi = acc[0] + bih[hcol]        + bhh[hcol];
    float gf = acc[1] + bih[HH + hcol]   + bhh[HH + hcol];
    float gg = acc[2] + bih[2*HH + hcol] + bhh[2*HH + hcol];
    float go = acc[3] + bih[3*HH + hcol] + bhh[3*HH + hcol];
    float cn = sigf(gf) * cin[b*HH + hcol] + sigf(gi) * tanhf(gg);
    float hn = sigf(go) * tanhf(cn);
    cout[b*HH + hcol] = cn;
    hout[b*HH + hcol] = hn;
    if (layer == 2) g_qstar[b*2*HH + hcol] = hn;
}

// ---------------- fused flash-style segment attention + last-block combine ----------------
// grid (BB, NCHUNK), 256 threads. The 16th chunk block of each segment performs the
// cross-chunk combine (fixed-order reads -> deterministic) and resets the counter.
__device__ __forceinline__ float dot_row_bf16(const uint4& v, const float* qb) {
    float2 h0 = __bfloat1622float2(*(__nv_bfloat162*)&v.x);
    float2 h1 = __bfloat1622float2(*(__nv_bfloat162*)&v.y);
    float2 h2 = __bfloat1622float2(*(__nv_bfloat162*)&v.z);
    float2 h3 = __bfloat1622float2(*(__nv_bfloat162*)&v.w);
    float sd = 0.f;
    sd = fmaf(h0.x, qb[0], sd); sd = fmaf(h0.y, qb[1], sd);
    sd = fmaf(h1.x, qb[2], sd); sd = fmaf(h1.y, qb[3], sd);
    sd = fmaf(h2.x, qb[4], sd); sd = fmaf(h2.y, qb[5], sd);
    sd = fmaf(h3.x, qb[6], sd); sd = fmaf(h3.y, qb[7], sd);
    return sd;
}

__global__ void __launch_bounds__(256)
attn_fused(int pw) {
    __shared__ float q[HH];
    __shared__ float se[TS];
    __shared__ float sw[TS];
    __shared__ float2 sacc[2][128];
    __shared__ unsigned s_old;
    __shared__ float sm8[NCHUNK], ss8[NCHUNK];
    int b = blockIdx.x, p = blockIdx.y, t = threadIdx.x;
    int lane = t & 31, wid = t >> 5;
    q[t] = g_h[(size_t)(pw*3 + 2)*BH + b*HH + t];
    __syncthreads();
    int s = g_seg[b], e = g_seg[b+1], len = e - s;
    int c0 = s + (int)(((long long)len * p) / NCHUNK);
    int c1 = s + (int)(((long long)len * (p + 1)) / NCHUNK);

    int half = t >> 7, tt = t & 127;
    float M = -INFINITY, S = 0.f;
    float2 acc = make_float2(0.f, 0.f);
    for (int t0 = c0; t0 < c1; t0 += TS) {
        int tl = min(TS, c1 - t0);
        // pass A: warp per row, 2-row ILP
        const float* qb = q + lane * 8;
        int i = wid;
        for (; i + 8 < tl; i += 16) {
            uint4 va = ((const uint4*)(g_hfb16 + (size_t)(t0 + i)     * (HH/2)))[lane];
            uint4 vb = ((const uint4*)(g_hfb16 + (size_t)(t0 + i + 8) * (HH/2)))[lane];
            float sda = dot_row_bf16(va, qb);
            float sdb = dot_row_bf16(vb, qb);
            #pragma unroll
            for (int o = 16; o > 0; o >>= 1) {
                sda += __shfl_xor_sync(0xffffffffu, sda, o);
                sdb += __shfl_xor_sync(0xffffffffu, sdb, o);
            }
            if (lane == 0) { se[i] = sda; se[i + 8] = sdb; }
        }
        for (; i < tl; i += 8) {
            uint4 v = ((const uint4*)(g_hfb16 + (size_t)(t0 + i) * (HH/2)))[lane];
            float sd = dot_row_bf16(v, qb);
            #pragma unroll
            for (int o = 16; o > 0; o >>= 1) sd += __shfl_xor_sync(0xffffffffu, sd, o);
            if (lane == 0) se[i] = sd;
        }
        __syncthreads();
        float mloc = -INFINITY;
        for (int k = 0; k < tl; k++) mloc = fmaxf(mloc, se[k]);
        float newM = fmaxf(M, mloc);
        float factor = expf(M - newM);
        if (t < tl) sw[t] = expf(se[t] - newM);
        acc.x *= factor; acc.y *= factor; S *= factor; M = newM;
        __syncthreads();
        for (int k = 0; k < tl; k++) S += sw[k];
        // pass B: rows split between halves, unroll x4
        const __nv_bfloat162* hb = g_hfb16 + tt;
        int j = half;
        for (; j + 6 < tl; j += 8) {
            float w0 = sw[j], w1 = sw[j+2], w2 = sw[j+4], w3 = sw[j+6];
            float2 h0 = __bfloat1622float2(hb[(size_t)(t0 + j)     * (HH/2)]);
            float2 h1 = __bfloat1622float2(hb[(size_t)(t0 + j + 2) * (HH/2)]);
            float2 h2 = __bfloat1622float2(hb[(size_t)(t0 + j + 4) * (HH/2)]);
            float2 h3 = __bfloat1622float2(hb[(size_t)(t0 + j + 6) * (HH/2)]);
            acc.x = fmaf(w0, h0.x, acc.x); acc.y = fmaf(w0, h0.y, acc.y);
            acc.x = fmaf(w1, h1.x, acc.x); acc.y = fmaf(w1, h1.y, acc.y);
            acc.x = fmaf(w2, h2.x, acc.x); acc.y = fmaf(w2, h2.y, acc.y);
            acc.x = fmaf(w3, h3.x, acc.x); acc.y = fmaf(w3, h3.y, acc.y);
        }
        for (; j < tl; j += 2) {
            float w = sw[j];
            float2 hv = __bfloat1622float2(hb[(size_t)(t0 + j) * (HH/2)]);
            acc.x = fmaf(w, hv.x, acc.x);
            acc.y = fmaf(w, hv.y, acc.y);
        }
        __syncthreads();
    }
    sacc[half][tt] = acc;
    __syncthreads();
    if (t < 128) {
        float2 a0 = sacc[0][t], a1 = sacc[1][t];
        float* dst = g_rpart + (size_t)(b * NCHUNK + p) * HH;
        dst[2*t]   = a0.x + a1.x;
        dst[2*t+1] = a0.y + a1.y;
    }
    if (t == 0) { g_spart[b * NCHUNK + p] = S; g_mpart[b * NCHUNK + p] = M; }

    // ---- last-block combine (threadFenceReduction pattern) ----
    __threadfence();
    __syncthreads();                 // all partial writes issued before the fence+atomic
    if (t == 0) s_old = atomicAdd(&g_ctr[b], 1u);
    __syncthreads();
    if (s_old == NCHUNK - 1) {
        if (t < NCHUNK) {
            sm8[t] = g_mpart[b * NCHUNK + t];
            ss8[t] = g_spart[b * NCHUNK + t];
        }
        __syncthreads();
        float Mg = -INFINITY;
        #pragma unroll
        for (int pp = 0; pp < NCHUNK; pp++) Mg = fmaxf(Mg, sm8[pp]);
        if (!isfinite(Mg)) Mg = 0.f;   // empty-segment guard (matches reference)
        float Sg = 0.f, r = 0.f;
        #pragma unroll
        for (int pp = 0; pp < NCHUNK; pp++) {
            float f = expf(sm8[pp] - Mg);
            Sg = fmaf(ss8[pp], f, Sg);
            r = fmaf(g_rpart[(size_t)(b * NCHUNK + pp) * HH + t], f, r);
        }
        g_qstar[b * 2 * HH + HH + t] = r / (Sg + 1e-16f);
        if (t == 0) g_ctr[b] = 0u;     // reset for next step
    }
}

// ---------------- output projection ----------------
__global__ void out_proj(const float* __restrict__ W, const float* __restrict__ bvec,
                         float* __restrict__ out) {
    __shared__ float qrow[2*HH];
    int b = blockIdx.x, t = threadIdx.x;    // 128 threads
    #pragma unroll
    for (int i = 0; i < 4; i++) qrow[t + i*128] = g_qstar[b*2*HH + t + i*128];
    __syncthreads();
    float acc = 0.f;
    #pragma unroll 8
    for (int k = 0; k < 2*HH; k++) acc = fmaf(qrow[k], W[k*EE + t], acc);
    out[b*EE + t] = acc + bvec[t];
}

// ---------------- launch ----------------
extern "C" void kernel_launch(void* const* d_in, const int* in_sizes, int n_in,
                              void* d_out, int out_size) {
    const float* x    = (const float*)d_in[0];
    const int*   bidx = (const int*)  d_in[1];
    const float* W1   = (const float*)d_in[2];
    const float* b1   = (const float*)d_in[3];
    const float* W2   = (const float*)d_in[4];
    const float* b2   = (const float*)d_in[5];
    const float* Wih[3] = {(const float*)d_in[6],  (const float*)d_in[10], (const float*)d_in[14]};
    const float* Whh[3] = {(const float*)d_in[7],  (const float*)d_in[11], (const float*)d_in[15]};
    const float* bih[3] = {(const float*)d_in[8],  (const float*)d_in[12], (const float*)d_in[16]};
    const float* bhh[3] = {(const float*)d_in[9],  (const float*)d_in[13], (const float*)d_in[17]};
    const float* outW = (const float*)d_in[18];
    const float* outb = (const float*)d_in[19];
    float* out = (float*)d_out;

    zero_state<<<(2*3*BH + 255)/256, 256>>>();
    seg_bounds<<<1, 256>>>(bidx);

    dim3 gfnn((NN + 127)/128, HH/128);
    fnn_gemm<0><<<gfnn, 256>>>(x, W1, b1);
    fnn_gemm<1><<<gfnn, 256>>>(x, W2, b2);   // A ignored in phase 1 (reads g_y1)

    dim3 gl(BB/8, HH/16);
    dim3 gw(BB, NCHUNK);
    for (int s = 0; s < NSTEPS; s++) {
        int pr = s & 1;
        for (int l = 0; l < 3; l++)
            lstm_fused<<<gl, 128>>>(l, pr, Wih[l], Whh[l], bih[l], bhh[l]);
        attn_fused<<<gw, 256>>>(pr ^ 1);
    }
    out_proj<<<BB, EE>>>(outW, outb, out);
}

// round 16
// speedup vs baseline: 1.1894x; 1.1067x over previous
#include <cuda_runtime.h>
#include <cuda_bf16.h>
#include <math.h>
#include <stdint.h>

#define NN 100000
#define DD 256
#define HH 256
#define BB 128
#define EE 128
#define NSTEPS 5
#define BH (BB*HH)
#define NCHUNK 16
#define TS 64

typedef unsigned long long ull;

// ---------------- scratch (static device globals; no allocations) ----------------
__device__ float g_y1[(size_t)NN*HH];              // FNN intermediate (fp32)
__device__ __nv_bfloat162 g_hfb16[(size_t)NN*HH/2]; // FNN output, bf16 packed
__device__ float g_h[2*3*BH];                      // ping-pong [parity][layer]
__device__ float g_c[2*3*BH];
__device__ float g_qstar[BB*2*HH];
__device__ float g_rpart[(size_t)BB*NCHUNK*HH];
__device__ float g_spart[BB*NCHUNK];
__device__ float g_mpart[BB*NCHUNK];
__device__ unsigned g_ctr[BB];                     // last-block-done counters
__device__ int   g_seg[BB+1];

// ---------------- helpers ----------------
__device__ __forceinline__ float sigf(float x) { return 1.f / (1.f + expf(-x)); }

__device__ __forceinline__ void ffma2(ull &d, ull a, ull b) {
    asm("fma.rn.f32x2 %0, %1, %2, %3;" : "=l"(d) : "l"(a), "l"(b), "l"(d));
}
__device__ __forceinline__ ull bcast2(float a) {
    ull r;
    asm("mov.b64 %0, {%1, %1};" : "=l"(r) : "f"(a));
    return r;
}
__device__ __forceinline__ void unpack2(ull v, float &x, float &y) {
    asm("mov.b64 {%0, %1}, %2;" : "=f"(x), "=f"(y) : "l"(v));
}

// ---------------- init ----------------
__global__ void zero_state() {
    int i = blockIdx.x * blockDim.x + threadIdx.x;
    if (i < 2*3*BH) { g_h[i] = 0.f; g_c[i] = 0.f; }
    if (i < BB*2*HH) g_qstar[i] = 0.f;
    if (i < BB) g_ctr[i] = 0u;
}

__global__ void seg_bounds(const int* __restrict__ idx) {
    int b = threadIdx.x;
    if (b > BB) return;
    int lo = 0, hi = NN;
    while (lo < hi) { int mid = (lo + hi) >> 1; if (idx[mid] < b) lo = mid + 1; else hi = mid; }
    g_seg[b] = lo;
}

// ---------------- FNN GEMM: proven round-12 FFMA2 kernel; phase 1 writes bf16 ----------------
template<int PHASE>
__global__ void __launch_bounds__(256, 2)
fnn_gemm(const float* __restrict__ Ax, const float* __restrict__ W,
         const float* __restrict__ bias) {
    const float* A = (PHASE == 0) ? Ax : g_y1;
    __shared__ float As[16*132];   // [k][m], padded stride 132
    __shared__ float Bs[16*128];   // [k][n]
    int tid = threadIdx.x;
    int m0 = blockIdx.x * 128;
    int n0 = blockIdx.y * 128;
    int tx = tid & 15, ty = tid >> 4;
    int c0 = tx * 8, r0 = ty * 8;
    int arow = tid >> 2;
    int akq  = (tid & 3) * 4;
    int bk   = tid >> 5;
    int bnq  = (tid & 31) * 4;

    ull acc[8][4];
    #pragma unroll
    for (int i = 0; i < 8; i++)
        #pragma unroll
        for (int j = 0; j < 4; j++) acc[i][j] = 0ull;

    float4 pa0, pa1, pb0, pb1;
    {
        int gm0 = m0 + arow, gm1 = m0 + arow + 64;
        pa0 = (gm0 < NN) ? *(const float4*)&A[(size_t)gm0*DD + akq] : make_float4(0,0,0,0);
        pa1 = (gm1 < NN) ? *(const float4*)&A[(size_t)gm1*DD + akq] : make_float4(0,0,0,0);
        pb0 = *(const float4*)&W[(size_t)bk*HH + n0 + bnq];
        pb1 = *(const float4*)&W[(size_t)(bk+8)*HH + n0 + bnq];
    }
    for (int kt = 0; kt < DD; kt += 16) {
        As[(akq+0)*132+arow] = pa0.x; As[(akq+1)*132+arow] = pa0.y;
        As[(akq+2)*132+arow] = pa0.z; As[(akq+3)*132+arow] = pa0.w;
        As[(akq+0)*132+arow+64] = pa1.x; As[(akq+1)*132+arow+64] = pa1.y;
        As[(akq+2)*132+arow+64] = pa1.z; As[(akq+3)*132+arow+64] = pa1.w;
        *(float4*)&Bs[bk*128 + bnq]     = pb0;
        *(float4*)&Bs[(bk+8)*128 + bnq] = pb1;
        __syncthreads();
        int kn = kt + 16;
        if (kn < DD) {
            int gm0 = m0 + arow, gm1 = m0 + arow + 64;
            pa0 = (gm0 < NN) ? *(const float4*)&A[(size_t)gm0*DD + kn + akq] : make_float4(0,0,0,0);
            pa1 = (gm1 < NN) ? *(const float4*)&A[(size_t)gm1*DD + kn + akq] : make_float4(0,0,0,0);
            pb0 = *(const float4*)&W[(size_t)(kn+bk)*HH + n0 + bnq];
            pb1 = *(const float4*)&W[(size_t)(kn+bk+8)*HH + n0 + bnq];
        }
        #pragma unroll
        for (int k = 0; k < 16; k++) {
            float a[8];
            *(float4*)&a[0] = *(const float4*)&As[k*132 + r0];
            *(float4*)&a[4] = *(const float4*)&As[k*132 + r0 + 4];
            ulonglong2 bq0 = *(const ulonglong2*)&Bs[k*128 + c0];
            ulonglong2 bq1 = *(const ulonglong2*)&Bs[k*128 + c0 + 4];
            ull bp0 = bq0.x, bp1 = bq0.y, bp2 = bq1.x, bp3 = bq1.y;
            #pragma unroll
            for (int i = 0; i < 8; i++) {
                ull ap = bcast2(a[i]);
                ffma2(acc[i][0], ap, bp0);
                ffma2(acc[i][1], ap, bp1);
                ffma2(acc[i][2], ap, bp2);
                ffma2(acc[i][3], ap, bp3);
            }
        }
        __syncthreads();
    }
    float bv[8];
    #pragma unroll
    for (int j = 0; j < 8; j++) bv[j] = bias[n0 + c0 + j];
    #pragma unroll
    for (int i = 0; i < 8; i++) {
        int gm = m0 + r0 + i;
        if (gm < NN) {
            float o[8];
            #pragma unroll
            for (int j = 0; j < 4; j++) {
                float x, y;
                unpack2(acc[i][j], x, y);
                float v0 = x + bv[2*j], v1 = y + bv[2*j+1];
                if (PHASE == 0) {
                    v0 = (v0 > 0.f) ? v0 : expm1f(v0);
                    v1 = (v1 > 0.f) ? v1 : expm1f(v1);
                }
                o[2*j] = v0; o[2*j+1] = v1;
            }
            if (PHASE == 0) {
                *(float4*)&g_y1[(size_t)gm*HH + n0 + c0]     = *(float4*)&o[0];
                *(float4*)&g_y1[(size_t)gm*HH + n0 + c0 + 4] = *(float4*)&o[4];
            } else {
                __nv_bfloat162 p0 = __float22bfloat162_rn(make_float2(o[0], o[1]));
                __nv_bfloat162 p1 = __float22bfloat162_rn(make_float2(o[2], o[3]));
                __nv_bfloat162 p2 = __float22bfloat162_rn(make_float2(o[4], o[5]));
                __nv_bfloat162 p3 = __float22bfloat162_rn(make_float2(o[6], o[7]));
                uint4 pk;
                pk.x = *(uint32_t*)&p0; pk.y = *(uint32_t*)&p1;
                pk.z = *(uint32_t*)&p2; pk.w = *(uint32_t*)&p3;
                *(uint4*)&g_hfb16[((size_t)gm*HH + n0 + c0) >> 1] = pk;
            }
        }
    }
}

// ---------------- fused LSTM layer: 2 batch rows per thread, tiled A, halved LDS ----------------
// grid (BB/16=8, HH/16=16) = 128 blocks, 128 threads. Thread (tx,ty) owns hcol
// t0+tx (4 gates) for batch rows b0+ty and b0+ty+8. Ws reuse across 2 rows gives
// 8 outputs per 16B LDS (was 4). A and W double-buffered through SMEM, 1 barrier/tile.
// Per-gate accumulation stays a single fp32 FMA chain in ascending k (bit-identical).
__global__ void __launch_bounds__(128)
lstm_fused(int layer, int pr,
           const float* __restrict__ Wih, const float* __restrict__ Whh,
           const float* __restrict__ bih, const float* __restrict__ bhh) {
    __shared__ float As2[2][16*36];   // [buf][row][k], padded stride 36
    __shared__ float Ws[2][32*68];    // [buf][k][j], j = 4*hcol_local + gate
    const int K1 = (layer == 0) ? 2*HH : HH;
    const int K  = K1 + HH;
    const int pw = pr ^ 1;
    const float* xin = (layer == 0) ? g_qstar : (g_h + (size_t)(pw*3 + (layer-1))*BH);
    const float* hin = g_h + (size_t)(pr*3 + layer)*BH;
    const float* cin = g_c + (size_t)(pr*3 + layer)*BH;
    float* hout = g_h + (size_t)(pw*3 + layer)*BH;
    float* cout = g_c + (size_t)(pw*3 + layer)*BH;
    int tid = threadIdx.x;
    int b0 = blockIdx.x * 16;
    int t0 = blockIdx.y * 16;        // h-column base
    int wj = tid >> 3;               // 0..15 (W load j base)
    int wk = (tid & 7) * 4;          // 0,4,..28 (W load k-quad)
    int arow = tid >> 3;             // 0..15 (A load row)
    int akq  = (tid & 7) * 4;        // 0,4,..28 (A load k-quad)

    float4 wreg[4], areg;
    // prefetch tile 0
    {
        const float* Wsrc = Wih; int stride = K1, kc = wk;
        #pragma unroll
        for (int p = 0; p < 4; p++) {
            int j = p*16 + wj;
            int grow = (j & 3) * HH + t0 + (j >> 2);
            wreg[p] = *(const float4*)&Wsrc[(size_t)grow*stride + kc];
        }
        areg = *(const float4*)&xin[(size_t)(b0 + arow)*K1 + akq];
    }
    // store tile 0
    #pragma unroll
    for (int p = 0; p < 4; p++) {
        int j = p*16 + wj;
        Ws[0][(wk+0)*68+j] = wreg[p].x; Ws[0][(wk+1)*68+j] = wreg[p].y;
        Ws[0][(wk+2)*68+j] = wreg[p].z; Ws[0][(wk+3)*68+j] = wreg[p].w;
    }
    *(float4*)&As2[0][arow*36 + akq] = areg;
    __syncthreads();

    int tx = tid & 15, ty = tid >> 4;   // ty 0..7
    int c0 = tx * 4;
    ull a00 = 0ull, a01 = 0ull, a10 = 0ull, a11 = 0ull;  // [row][(i,f)/(g,o)]
    for (int kt = 0; kt < K; kt += 32) {
        int buf = (kt >> 5) & 1;
        bool more = (kt + 32) < K;
        if (more) {
            int ktn = kt + 32;
            // W prefetch
            const float* Wsrc; int stride, kc;
            if (ktn < K1) { Wsrc = Wih; stride = K1; kc = ktn + wk; }
            else          { Wsrc = Whh; stride = HH; kc = ktn - K1 + wk; }
            #pragma unroll
            for (int p = 0; p < 4; p++) {
                int j = p*16 + wj;
                int grow = (j & 3) * HH + t0 + (j >> 2);
                wreg[p] = *(const float4*)&Wsrc[(size_t)grow*stride + kc];
            }
            // A prefetch
            int ka = ktn + akq;
            if (ka < K1) areg = *(const float4*)&xin[(size_t)(b0 + arow)*K1 + ka];
            else         areg = *(const float4*)&hin[(size_t)(b0 + arow)*HH + (ka - K1)];
        }
        const float* Wb = Ws[buf];
        const float* ar0 = &As2[buf][(size_t)ty*36];
        const float* ar1 = &As2[buf][(size_t)(ty + 8)*36];
        #pragma unroll
        for (int k = 0; k < 32; k++) {
            ulonglong2 bq = *(const ulonglong2*)&Wb[k*68 + c0];
            ull p0 = bcast2(ar0[k]);
            ull p1 = bcast2(ar1[k]);
            ffma2(a00, p0, bq.x);
            ffma2(a01, p0, bq.y);
            ffma2(a10, p1, bq.x);
            ffma2(a11, p1, bq.y);
        }
        if (more) {
            float* Wn = Ws[buf ^ 1];
            #pragma unroll
            for (int p = 0; p < 4; p++) {
                int j = p*16 + wj;
                Wn[(wk+0)*68+j] = wreg[p].x; Wn[(wk+1)*68+j] = wreg[p].y;
                Wn[(wk+2)*68+j] = wreg[p].z; Wn[(wk+3)*68+j] = wreg[p].w;
            }
            *(float4*)&As2[buf ^ 1][arow*36 + akq] = areg;
        }
        __syncthreads();
    }
    int hcol = t0 + tx;
    float bi0 = bih[hcol]        + bhh[hcol];
    float bf0 = bih[HH + hcol]   + bhh[HH + hcol];
    float bg0 = bih[2*HH + hcol] + bhh[2*HH + hcol];
    float bo0 = bih[3*HH + hcol] + bhh[3*HH + hcol];
    ull accr[2][2] = {{a00, a01}, {a10, a11}};
    #pragma unroll
    for (int r = 0; r < 2; r++) {
        int b = b0 + ty + 8 * r;
        float gi, gf, gg, go;
        unpack2(accr[r][0], gi, gf);
        unpack2(accr[r][1], gg, go);
        gi += bi0; gf += bf0; gg += bg0; go += bo0;
        float cn = sigf(gf) * cin[b*HH + hcol] + sigf(gi) * tanhf(gg);
        float hn = sigf(go) * tanhf(cn);
        cout[b*HH + hcol] = cn;
        hout[b*HH + hcol] = hn;
        if (layer == 2) g_qstar[b*2*HH + hcol] = hn;
    }
}

// ---------------- fused flash-style segment attention + last-block combine ----------------
__device__ __forceinline__ float dot_row_bf16(const uint4& v, const float* qb) {
    float2 h0 = __bfloat1622float2(*(__nv_bfloat162*)&v.x);
    float2 h1 = __bfloat1622float2(*(__nv_bfloat162*)&v.y);
    float2 h2 = __bfloat1622float2(*(__nv_bfloat162*)&v.z);
    float2 h3 = __bfloat1622float2(*(__nv_bfloat162*)&v.w);
    float sd = 0.f;
    sd = fmaf(h0.x, qb[0], sd); sd = fmaf(h0.y, qb[1], sd);
    sd = fmaf(h1.x, qb[2], sd); sd = fmaf(h1.y, qb[3], sd);
    sd = fmaf(h2.x, qb[4], sd); sd = fmaf(h2.y, qb[5], sd);
    sd = fmaf(h3.x, qb[6], sd); sd = fmaf(h3.y, qb[7], sd);
    return sd;
}

__global__ void __launch_bounds__(256)
attn_fused(int pw) {
    __shared__ float q[HH];
    __shared__ float se[TS];
    __shared__ float sw[TS];
    __shared__ float2 sacc[2][128];
    __shared__ unsigned s_old;
    __shared__ float sm8[NCHUNK], ss8[NCHUNK];
    int b = blockIdx.x, p = blockIdx.y, t = threadIdx.x;
    int lane = t & 31, wid = t >> 5;
    q[t] = g_h[(size_t)(pw*3 + 2)*BH + b*HH + t];
    __syncthreads();
    int s = g_seg[b], e = g_seg[b+1], len = e - s;
    int c0 = s + (int)(((long long)len * p) / NCHUNK);
    int c1 = s + (int)(((long long)len * (p + 1)) / NCHUNK);

    int half = t >> 7, tt = t & 127;
    float M = -INFINITY, S = 0.f;
    float2 acc = make_float2(0.f, 0.f);
    for (int t0 = c0; t0 < c1; t0 += TS) {
        int tl = min(TS, c1 - t0);
        const float* qb = q + lane * 8;
        int i = wid;
        for (; i + 8 < tl; i += 16) {
            uint4 va = ((const uint4*)(g_hfb16 + (size_t)(t0 + i)     * (HH/2)))[lane];
            uint4 vb = ((const uint4*)(g_hfb16 + (size_t)(t0 + i + 8) * (HH/2)))[lane];
            float sda = dot_row_bf16(va, qb);
            float sdb = dot_row_bf16(vb, qb);
            #pragma unroll
            for (int o = 16; o > 0; o >>= 1) {
                sda += __shfl_xor_sync(0xffffffffu, sda, o);
                sdb += __shfl_xor_sync(0xffffffffu, sdb, o);
            }
            if (lane == 0) { se[i] = sda; se[i + 8] = sdb; }
        }
        for (; i < tl; i += 8) {
            uint4 v = ((const uint4*)(g_hfb16 + (size_t)(t0 + i) * (HH/2)))[lane];
            float sd = dot_row_bf16(v, qb);
            #pragma unroll
            for (int o = 16; o > 0; o >>= 1) sd += __shfl_xor_sync(0xffffffffu, sd, o);
            if (lane == 0) se[i] = sd;
        }
        __syncthreads();
        float mloc = -INFINITY;
        for (int k = 0; k < tl; k++) mloc = fmaxf(mloc, se[k]);
        float newM = fmaxf(M, mloc);
        float factor = expf(M - newM);
        if (t < tl) sw[t] = expf(se[t] - newM);
        acc.x *= factor; acc.y *= factor; S *= factor; M = newM;
        __syncthreads();
        for (int k = 0; k < tl; k++) S += sw[k];
        const __nv_bfloat162* hb = g_hfb16 + tt;
        int j = half;
        for (; j + 6 < tl; j += 8) {
            float w0 = sw[j], w1 = sw[j+2], w2 = sw[j+4], w3 = sw[j+6];
            float2 h0 = __bfloat1622float2(hb[(size_t)(t0 + j)     * (HH/2)]);
            float2 h1 = __bfloat1622float2(hb[(size_t)(t0 + j + 2) * (HH/2)]);
            float2 h2 = __bfloat1622float2(hb[(size_t)(t0 + j + 4) * (HH/2)]);
            float2 h3 = __bfloat1622float2(hb[(size_t)(t0 + j + 6) * (HH/2)]);
            acc.x = fmaf(w0, h0.x, acc.x); acc.y = fmaf(w0, h0.y, acc.y);
            acc.x = fmaf(w1, h1.x, acc.x); acc.y = fmaf(w1, h1.y, acc.y);
            acc.x = fmaf(w2, h2.x, acc.x); acc.y = fmaf(w2, h2.y, acc.y);
            acc.x = fmaf(w3, h3.x, acc.x); acc.y = fmaf(w3, h3.y, acc.y);
        }
        for (; j < tl; j += 2) {
            float w = sw[j];
            float2 hv = __bfloat1622float2(hb[(size_t)(t0 + j) * (HH/2)]);
            acc.x = fmaf(w, hv.x, acc.x);
            acc.y = fmaf(w, hv.y, acc.y);
        }
        __syncthreads();
    }
    sacc[half][tt] = acc;
    __syncthreads();
    if (t < 128) {
        float2 a0 = sacc[0][t], a1 = sacc[1][t];
        float* dst = g_rpart + (size_t)(b * NCHUNK + p) * HH;
        dst[2*t]   = a0.x + a1.x;
        dst[2*t+1] = a0.y + a1.y;
    }
    if (t == 0) { g_spart[b * NCHUNK + p] = S; g_mpart[b * NCHUNK + p] = M; }

    // ---- last-block combine (threadFenceReduction pattern) ----
    __threadfence();
    __syncthreads();
    if (t == 0) s_old = atomicAdd(&g_ctr[b], 1u);
    __syncthreads();
    if (s_old == NCHUNK - 1) {
        if (t < NCHUNK) {
            sm8[t] = g_mpart[b * NCHUNK + t];
            ss8[t] = g_spart[b * NCHUNK + t];
        }
        __syncthreads();
        float Mg = -INFINITY;
        #pragma unroll
        for (int pp = 0; pp < NCHUNK; pp++) Mg = fmaxf(Mg, sm8[pp]);
        if (!isfinite(Mg)) Mg = 0.f;   // empty-segment guard (matches reference)
        float Sg = 0.f, r = 0.f;
        #pragma unroll
        for (int pp = 0; pp < NCHUNK; pp++) {
            float f = expf(sm8[pp] - Mg);
            Sg = fmaf(ss8[pp], f, Sg);
            r = fmaf(g_rpart[(size_t)(b * NCHUNK + pp) * HH + t], f, r);
        }
        g_qstar[b * 2 * HH + HH + t] = r / (Sg + 1e-16f);
        if (t == 0) g_ctr[b] = 0u;     // reset for next step
    }
}

// ---------------- output projection ----------------
__global__ void out_proj(const float* __restrict__ W, const float* __restrict__ bvec,
                         float* __restrict__ out) {
    __shared__ float qrow[2*HH];
    int b = blockIdx.x, t = threadIdx.x;    // 128 threads
    #pragma unroll
    for (int i = 0; i < 4; i++) qrow[t + i*128] = g_qstar[b*2*HH + t + i*128];
    __syncthreads();
    float acc = 0.f;
    #pragma unroll 8
    for (int k = 0; k < 2*HH; k++) acc = fmaf(qrow[k], W[k*EE + t], acc);
    out[b*EE + t] = acc + bvec[t];
}

// ---------------- launch ----------------
extern "C" void kernel_launch(void* const* d_in, const int* in_sizes, int n_in,
                              void* d_out, int out_size) {
    const float* x    = (const float*)d_in[0];
    const int*   bidx = (const int*)  d_in[1];
    const float* W1   = (const float*)d_in[2];
    const float* b1   = (const float*)d_in[3];
    const float* W2   = (const float*)d_in[4];
    const float* b2   = (const float*)d_in[5];
    const float* Wih[3] = {(const float*)d_in[6],  (const float*)d_in[10], (const float*)d_in[14]};
    const float* Whh[3] = {(const float*)d_in[7],  (const float*)d_in[11], (const float*)d_in[15]};
    const float* bih[3] = {(const float*)d_in[8],  (const float*)d_in[12], (const float*)d_in[16]};
    const float* bhh[3] = {(const float*)d_in[9],  (const float*)d_in[13], (const float*)d_in[17]};
    const float* outW = (const float*)d_in[18];
    const float* outb = (const float*)d_in[19];
    float* out = (float*)d_out;

    zero_state<<<(2*3*BH + 255)/256, 256>>>();
    seg_bounds<<<1, 256>>>(bidx);

    dim3 gfnn((NN + 127)/128, HH/128);
    fnn_gemm<0><<<gfnn, 256>>>(x, W1, b1);
    fnn_gemm<1><<<gfnn, 256>>>(x, W2, b2);   // A ignored in phase 1 (reads g_y1)

    dim3 gl(BB/16, HH/16);
    dim3 gw(BB, NCHUNK);
    for (int s = 0; s < NSTEPS; s++) {
        int pr = s & 1;
        for (int l = 0; l < 3; l++)
            lstm_fused<<<gl, 128>>>(l, pr, Wih[l], Whh[l], bih[l], bhh[l]);
        attn_fused<<<gw, 256>>>(pr ^ 1);
    }
    out_proj<<<BB, EE>>>(outW, outb, out);
}